// round 1
// baseline (speedup 1.0000x reference)
#include <cuda_runtime.h>
#include <math.h>

#define BATCH 512
#define SEQ   512
#define EMBED 256
#define OUTC  5
#define EV4   (EMBED / 4)   // 64 float4 per embedding row

// Per-sample loss scratch (no device mallocs allowed)
__device__ float g_loss[BATCH];

__device__ __forceinline__ void acc4(float4& a, const float4& v) {
    a.x += v.x; a.y += v.y; a.z += v.z; a.w += v.w;
}

__global__ __launch_bounds__(256, 4)
void pool_loss_kernel(const int*   __restrict__ input_x,
                      const int*   __restrict__ lengths,
                      const int*   __restrict__ input_y,
                      const float* __restrict__ emb,
                      const float* __restrict__ W,
                      const float* __restrict__ bias)
{
    __shared__ int    s_idx[SEQ];
    __shared__ float4 s_acc[256];
    __shared__ float  s_red[OUTC][2];

    const int b   = blockIdx.x;
    const int tid = threadIdx.x;
    const int len = lengths[b];

    // Stage this sample's token ids in shared (2 KB)
    const int* xrow = input_x + b * SEQ;
    s_idx[tid]       = xrow[tid];
    s_idx[tid + 256] = xrow[tid + 256];
    __syncthreads();

    const int g = tid >> 6;   // token group 0..3
    const int l = tid & 63;   // float4 lane within row

    const float4* __restrict__ embv = (const float4*)emb;

    float4 a0 = make_float4(0.f, 0.f, 0.f, 0.f);
    float4 a1 = make_float4(0.f, 0.f, 0.f, 0.f);
    float4 a2 = make_float4(0.f, 0.f, 0.f, 0.f);
    float4 a3 = make_float4(0.f, 0.f, 0.f, 0.f);

    int s = g;
    // Main loop: 4 independent gathers in flight per thread (MLP=4)
    for (; s + 12 < len; s += 16) {
        const int t0 = s_idx[s];
        const int t1 = s_idx[s + 4];
        const int t2 = s_idx[s + 8];
        const int t3 = s_idx[s + 12];
        float4 v0 = embv[(long)t0 * EV4 + l];
        float4 v1 = embv[(long)t1 * EV4 + l];
        float4 v2 = embv[(long)t2 * EV4 + l];
        float4 v3 = embv[(long)t3 * EV4 + l];
        acc4(a0, v0); acc4(a1, v1); acc4(a2, v2); acc4(a3, v3);
    }
    // Tail
    for (; s < len; s += 4) {
        const int t = s_idx[s];
        float4 v = embv[(long)t * EV4 + l];
        acc4(a0, v);
    }
    acc4(a0, a1); acc4(a2, a3); acc4(a0, a2);

    s_acc[tid] = a0;
    __syncthreads();

    // Warps 0-1 (tid < 64): combine groups, dot with W
    float part[OUTC];
    if (tid < 64) {
        float4 p0 = s_acc[l];
        float4 p1 = s_acc[64 + l];
        float4 p2 = s_acc[128 + l];
        float4 p3 = s_acc[192 + l];
        float4 pooled;
        pooled.x = (p0.x + p1.x) + (p2.x + p3.x);
        pooled.y = (p0.y + p1.y) + (p2.y + p3.y);
        pooled.z = (p0.z + p1.z) + (p2.z + p3.z);
        pooled.w = (p0.w + p1.w) + (p2.w + p3.w);

        const float4* __restrict__ Wv = (const float4*)W;
        #pragma unroll
        for (int o = 0; o < OUTC; o++) {
            float4 w = Wv[o * EV4 + l];
            part[o] = pooled.x * w.x + pooled.y * w.y
                    + pooled.z * w.z + pooled.w * w.w;
        }
        // Warp-level tree reduction over 32 lanes
        #pragma unroll
        for (int o = 0; o < OUTC; o++) {
            float v = part[o];
            #pragma unroll
            for (int off = 16; off > 0; off >>= 1)
                v += __shfl_down_sync(0xffffffffu, v, off);
            part[o] = v;
        }
        if ((tid & 31) == 0) {
            const int w = tid >> 5;  // 0 or 1
            #pragma unroll
            for (int o = 0; o < OUTC; o++) s_red[o][w] = part[o];
        }
    }
    __syncthreads();

    if (tid == 0) {
        const float inv_len = 1.0f / (float)len;
        float logits[OUTC];
        float m = -INFINITY;
        #pragma unroll
        for (int o = 0; o < OUTC; o++) {
            logits[o] = (s_red[o][0] + s_red[o][1]) * inv_len + bias[o];
            m = fmaxf(m, logits[o]);
        }
        float se = 0.f;
        #pragma unroll
        for (int o = 0; o < OUTC; o++) se += __expf(logits[o] - m);
        const float lse = m + __logf(se);
        const int y = input_y[b];
        g_loss[b] = lse - logits[y];
    }
}

__global__ __launch_bounds__(512)
void reduce_kernel(float* __restrict__ out)
{
    __shared__ float sh[512];
    const int t = threadIdx.x;
    sh[t] = g_loss[t];
    __syncthreads();
    #pragma unroll
    for (int off = 256; off > 0; off >>= 1) {
        if (t < off) sh[t] += sh[t + off];
        __syncthreads();
    }
    if (t == 0) out[0] = sh[0] * (1.0f / (float)BATCH);
}

extern "C" void kernel_launch(void* const* d_in, const int* in_sizes, int n_in,
                              void* d_out, int out_size)
{
    const int*   input_x = (const int*)d_in[0];
    const int*   lengths = (const int*)d_in[1];
    const int*   input_y = (const int*)d_in[2];
    const float* emb     = (const float*)d_in[3];
    const float* W       = (const float*)d_in[4];
    const float* bias    = (const float*)d_in[5];
    float* out = (float*)d_out;

    pool_loss_kernel<<<BATCH, 256>>>(input_x, lengths, input_y, emb, W, bias);
    reduce_kernel<<<1, 512>>>(out);
}

// round 2
// speedup vs baseline: 1.0284x; 1.0284x over previous
#include <cuda_runtime.h>
#include <math.h>

#define BATCH 512
#define SEQ   512
#define EMBED 256
#define OUTC  5
#define EV4   (EMBED / 4)   // 64 float4 per embedding row

// Scratch (device mallocs forbidden). g_count is zero-initialized at module
// load and reset to 0 by the last block on every call -> graph-replay safe.
__device__ float        g_loss[BATCH];
__device__ unsigned int g_count;

__device__ __forceinline__ void acc4(float4& a, const float4& v) {
    a.x += v.x; a.y += v.y; a.z += v.z; a.w += v.w;
}

__global__ __launch_bounds__(256, 4)
void pool_loss_kernel(const int*   __restrict__ input_x,
                      const int*   __restrict__ lengths,
                      const int*   __restrict__ input_y,
                      const float* __restrict__ emb,
                      const float* __restrict__ W,
                      const float* __restrict__ bias,
                      float*       __restrict__ out)
{
    __shared__ int    s_idx[SEQ];
    __shared__ float4 s_acc[256];
    __shared__ float  s_red[OUTC][2];
    __shared__ float  s_sum[256];
    __shared__ int    s_last;

    const int b   = blockIdx.x;
    const int tid = threadIdx.x;
    const int len = lengths[b];

    // Stage this sample's token ids in shared (2 KB)
    const int* xrow = input_x + b * SEQ;
    s_idx[tid]       = xrow[tid];
    s_idx[tid + 256] = xrow[tid + 256];
    __syncthreads();

    const int g = tid >> 6;   // token group 0..3
    const int l = tid & 63;   // float4 lane within row

    const float4* __restrict__ embv = (const float4*)emb;

    float4 a0 = make_float4(0.f, 0.f, 0.f, 0.f);
    float4 a1 = make_float4(0.f, 0.f, 0.f, 0.f);
    float4 a2 = make_float4(0.f, 0.f, 0.f, 0.f);
    float4 a3 = make_float4(0.f, 0.f, 0.f, 0.f);

    int s = g;
    // Main loop: 4 independent gathers in flight per thread (MLP=4)
    for (; s + 12 < len; s += 16) {
        const int t0 = s_idx[s];
        const int t1 = s_idx[s + 4];
        const int t2 = s_idx[s + 8];
        const int t3 = s_idx[s + 12];
        float4 v0 = embv[(long)t0 * EV4 + l];
        float4 v1 = embv[(long)t1 * EV4 + l];
        float4 v2 = embv[(long)t2 * EV4 + l];
        float4 v3 = embv[(long)t3 * EV4 + l];
        acc4(a0, v0); acc4(a1, v1); acc4(a2, v2); acc4(a3, v3);
    }
    // Tail
    for (; s < len; s += 4) {
        const int t = s_idx[s];
        float4 v = embv[(long)t * EV4 + l];
        acc4(a0, v);
    }
    acc4(a0, a1); acc4(a2, a3); acc4(a0, a2);

    s_acc[tid] = a0;
    __syncthreads();

    // Warps 0-1 (tid < 64): combine groups, dot with W
    float part[OUTC];
    if (tid < 64) {
        float4 p0 = s_acc[l];
        float4 p1 = s_acc[64 + l];
        float4 p2 = s_acc[128 + l];
        float4 p3 = s_acc[192 + l];
        float4 pooled;
        pooled.x = (p0.x + p1.x) + (p2.x + p3.x);
        pooled.y = (p0.y + p1.y) + (p2.y + p3.y);
        pooled.z = (p0.z + p1.z) + (p2.z + p3.z);
        pooled.w = (p0.w + p1.w) + (p2.w + p3.w);

        const float4* __restrict__ Wv = (const float4*)W;
        #pragma unroll
        for (int o = 0; o < OUTC; o++) {
            float4 w = Wv[o * EV4 + l];
            part[o] = pooled.x * w.x + pooled.y * w.y
                    + pooled.z * w.z + pooled.w * w.w;
        }
        // Warp-level tree reduction over 32 lanes
        #pragma unroll
        for (int o = 0; o < OUTC; o++) {
            float v = part[o];
            #pragma unroll
            for (int off = 16; off > 0; off >>= 1)
                v += __shfl_down_sync(0xffffffffu, v, off);
            part[o] = v;
        }
        if ((tid & 31) == 0) {
            const int w = tid >> 5;  // 0 or 1
            #pragma unroll
            for (int o = 0; o < OUTC; o++) s_red[o][w] = part[o];
        }
    }
    __syncthreads();

    // Per-sample loss + last-block handoff
    if (tid == 0) {
        const float inv_len = 1.0f / (float)len;
        float logits[OUTC];
        float m = -INFINITY;
        #pragma unroll
        for (int o = 0; o < OUTC; o++) {
            logits[o] = (s_red[o][0] + s_red[o][1]) * inv_len + bias[o];
            m = fmaxf(m, logits[o]);
        }
        float se = 0.f;
        #pragma unroll
        for (int o = 0; o < OUTC; o++) se += __expf(logits[o] - m);
        const float lse = m + __logf(se);
        const int y = input_y[b];
        g_loss[b] = lse - logits[y];
        __threadfence();                       // make g_loss[b] visible
        unsigned int old = atomicAdd(&g_count, 1u);
        s_last = (old == BATCH - 1) ? 1 : 0;
    }
    __syncthreads();

    // The last block to finish performs the final mean-reduction
    if (s_last) {
        s_sum[tid] = g_loss[tid] + g_loss[tid + 256];
        __syncthreads();
        #pragma unroll
        for (int off = 128; off > 0; off >>= 1) {
            if (tid < off) s_sum[tid] += s_sum[tid + off];
            __syncthreads();
        }
        if (tid == 0) {
            out[0] = s_sum[0] * (1.0f / (float)BATCH);
            g_count = 0;                       // reset for next graph replay
        }
    }
}

extern "C" void kernel_launch(void* const* d_in, const int* in_sizes, int n_in,
                              void* d_out, int out_size)
{
    const int*   input_x = (const int*)d_in[0];
    const int*   lengths = (const int*)d_in[1];
    const int*   input_y = (const int*)d_in[2];
    const float* emb     = (const float*)d_in[3];
    const float* W       = (const float*)d_in[4];
    const float* bias    = (const float*)d_in[5];
    float* out = (float*)d_out;

    pool_loss_kernel<<<BATCH, 256>>>(input_x, lengths, input_y, emb, W, bias, out);
}